// round 1
// baseline (speedup 1.0000x reference)
#include <cuda_runtime.h>
#include <cuda_bf16.h>
#include <cstdint>

// ---------------------------------------------------------------------------
// FeatherNet: Vf = V1@V2, then 3-layer MLP using slices of Vf as weights.
//   SIZE_N=5794, SIZE_M=2897, BATCH=4096, D_IN=2048, D_H=4096, D_OUT=2048
// Round 1: plain fp32 tiled SGEMM (correctness baseline).
// ---------------------------------------------------------------------------

#define SIZE_N 5794
#define SIZE_M 2897
#define BATCH  4096
#define D_IN   2048
#define D_H    4096
#define D_OUT  2048

// Offsets of weights/biases inside flattened Vf (row-major [SIZE_N, SIZE_N])
#define OFF_W1 0
#define OFF_B1 8388608      // W1: 4096*2048
#define OFF_W2 8392704      // +4096
#define OFF_B2 25169920     // +4096*4096
#define OFF_W3 25174016     // +4096
#define OFF_B3 33562624     // +2048*4096

// Scratch (device globals — allocation-free per harness rules)
__device__ float g_Vf[(size_t)SIZE_N * SIZE_N];   // 33,570,436 floats (~134 MB)
__device__ float g_h1[(size_t)BATCH * D_H];       // 67 MB
__device__ float g_h2[(size_t)BATCH * D_H];       // 67 MB

#define BM 128
#define BN 128
#define BK 16
#define TM 8
#define TN 8
// 256 threads: tx in [0,16) covers N, ty in [0,16) covers M; each thread does
// two 4-wide strips per dim (offsets 0 and 64) -> 8x8 microtile.

// C[m,n] = sum_k A[m,k] * op(B)[k,n]  (+bias[n]) (relu)
//   TRANS_B=true : B stored [N,K] row-major (weight matrices, NT gemm)
//   TRANS_B=false: B stored [K,N] row-major (V2, NN gemm)
template<bool TRANS_B, bool BIAS, bool RELU>
__global__ __launch_bounds__(256)
void gemm_kernel(const float* __restrict__ A, const float* __restrict__ B,
                 const float* __restrict__ bias, float* __restrict__ C,
                 int M, int N, int K)
{
    __shared__ float As[BK][BM + 4];
    __shared__ float Bs[BK][BN + 4];

    const int tid = threadIdx.x;
    const int tx = tid & 15;   // N direction
    const int ty = tid >> 4;   // M direction
    const int bm = blockIdx.y * BM;
    const int bn = blockIdx.x * BN;

    float acc[TM][TN];
#pragma unroll
    for (int i = 0; i < TM; i++)
#pragma unroll
        for (int j = 0; j < TN; j++) acc[i][j] = 0.0f;

    for (int k0 = 0; k0 < K; k0 += BK) {
        // ---- Load A tile [BM x BK] (row-major [M,K]) -> As[k][m], guarded ----
#pragma unroll
        for (int i = 0; i < (BM * BK) / 256; i++) {
            int e = tid + i * 256;
            int r = e / BK, c = e % BK;      // r: m-within-tile, c: k-within-tile
            int gm = bm + r, gk = k0 + c;
            float v = 0.0f;
            if (gm < M && gk < K) v = A[(size_t)gm * K + gk];
            As[c][r] = v;
        }
        // ---- Load B tile -> Bs[k][n], guarded ----
        if (TRANS_B) {
#pragma unroll
            for (int i = 0; i < (BN * BK) / 256; i++) {
                int e = tid + i * 256;
                int r = e / BK, c = e % BK;  // r: n-within-tile, c: k
                int gn = bn + r, gk = k0 + c;
                float v = 0.0f;
                if (gn < N && gk < K) v = B[(size_t)gn * K + gk];
                Bs[c][r] = v;
            }
        } else {
#pragma unroll
            for (int i = 0; i < (BK * BN) / 256; i++) {
                int e = tid + i * 256;
                int r = e / BN, c = e % BN;  // r: k, c: n (coalesced along N)
                int gk = k0 + r, gn = bn + c;
                float v = 0.0f;
                if (gk < K && gn < N) v = B[(size_t)gk * N + gn];
                Bs[r][c] = v;
            }
        }
        __syncthreads();

        // ---- Compute: outer products over BK ----
#pragma unroll
        for (int k = 0; k < BK; k++) {
            float ra[TM], rb[TN];
#pragma unroll
            for (int i = 0; i < 4; i++) {
                ra[i]     = As[k][ty * 4 + i];
                ra[4 + i] = As[k][64 + ty * 4 + i];
            }
#pragma unroll
            for (int j = 0; j < 4; j++) {
                rb[j]     = Bs[k][tx * 4 + j];
                rb[4 + j] = Bs[k][64 + tx * 4 + j];
            }
#pragma unroll
            for (int i = 0; i < TM; i++)
#pragma unroll
                for (int j = 0; j < TN; j++)
                    acc[i][j] = fmaf(ra[i], rb[j], acc[i][j]);
        }
        __syncthreads();
    }

    // ---- Epilogue: bias + relu + guarded store ----
#pragma unroll
    for (int i = 0; i < TM; i++) {
        int mi = (i < 4) ? (ty * 4 + i) : (64 + ty * 4 + (i - 4));
        int gm = bm + mi;
        if (gm >= M) continue;
#pragma unroll
        for (int j = 0; j < TN; j++) {
            int nj = (j < 4) ? (tx * 4 + j) : (64 + tx * 4 + (j - 4));
            int gn = bn + nj;
            if (gn >= N) continue;
            float v = acc[i][j];
            if (BIAS) v += __ldg(&bias[gn]);
            if (RELU) v = fmaxf(v, 0.0f);
            C[(size_t)gm * N + gn] = v;
        }
    }
}

static inline dim3 grid_for(int M, int N) {
    return dim3((N + BN - 1) / BN, (M + BM - 1) / BM);
}

extern "C" void kernel_launch(void* const* d_in, const int* in_sizes, int n_in,
                              void* d_out, int out_size)
{
    const float* x  = (const float*)d_in[0];   // [4096, 2048]
    const float* V1 = (const float*)d_in[1];   // [5794, 2897]
    const float* V2 = (const float*)d_in[2];   // [2897, 5794]
    float* out = (float*)d_out;                // [4096, 2048]

    float *Vf, *h1, *h2;
    cudaGetSymbolAddress((void**)&Vf, g_Vf);
    cudaGetSymbolAddress((void**)&h1, g_h1);
    cudaGetSymbolAddress((void**)&h2, g_h2);

    // 1) Vf = V1 @ V2   (NN)  [5794 x 5794], K=2897
    gemm_kernel<false, false, false><<<grid_for(SIZE_N, SIZE_N), 256>>>(
        V1, V2, nullptr, Vf, SIZE_N, SIZE_N, SIZE_M);

    // 2) h1 = relu(x @ W1^T + b1)   (NT)  M=4096, N=4096, K=2048
    gemm_kernel<true, true, true><<<grid_for(BATCH, D_H), 256>>>(
        x, Vf + OFF_W1, Vf + OFF_B1, h1, BATCH, D_H, D_IN);

    // 3) h2 = relu(h1 @ W2^T + b2)  (NT)  M=4096, N=4096, K=4096
    gemm_kernel<true, true, true><<<grid_for(BATCH, D_H), 256>>>(
        h1, Vf + OFF_W2, Vf + OFF_B2, h2, BATCH, D_H, D_H);

    // 4) out = h2 @ W3^T + b3       (NT)  M=4096, N=2048, K=4096
    gemm_kernel<true, true, false><<<grid_for(BATCH, D_OUT), 256>>>(
        h2, Vf + OFF_W3, Vf + OFF_B3, out, BATCH, D_OUT, D_H);
}

// round 3
// speedup vs baseline: 5.3226x; 5.3226x over previous
#include <cuda_runtime.h>
#include <cuda_bf16.h>
#include <cstdint>

// ---------------------------------------------------------------------------
// FeatherNet via warp-level mma.sync tf32 (generic PTX; no 'a'-features):
//   Vf = V1@V2 ; h1 = relu(x W1^T + b1); h2 = relu(h1 W2^T + b2); out = h2 W3^T + b3
// All 4 GEMMs are NT: C[M,N] = A[M,K] * B[N,K]^T.
// ---------------------------------------------------------------------------

#define SIZE_N 5794
#define SIZE_M 2897
#define K_PAD  2912        // 91 * 32
#define BATCH  4096
#define D_IN   2048
#define D_H    4096
#define D_OUT  2048

#define OFF_W1 0
#define OFF_B1 8388608
#define OFF_W2 8392704
#define OFF_B2 25169920
#define OFF_W3 25174016
#define OFF_B3 33562624

__device__ __align__(256) float g_V1r[(size_t)SIZE_N * K_PAD];
__device__ __align__(256) float g_V2T[(size_t)SIZE_N * K_PAD];
__device__ __align__(256) float g_xr [(size_t)BATCH * D_IN];
__device__ __align__(256) float g_Vf [(size_t)SIZE_N * SIZE_N];
__device__ __align__(256) float g_h1 [(size_t)BATCH * D_H];
__device__ __align__(256) float g_h2 [(size_t)BATCH * D_H];

// ============================ helpers =======================================

__device__ __forceinline__ float rna_tf32(float v) {
    uint32_t u;
    asm("cvt.rna.tf32.f32 %0, %1;" : "=r"(u) : "f"(v));
    return __uint_as_float(u);
}

__device__ __forceinline__ uint32_t smem_u32(const void* p) {
    uint32_t a;
    asm("{ .reg .u64 t; cvta.to.shared.u64 t, %1; cvt.u32.u64 %0, t; }"
        : "=r"(a) : "l"(p));
    return a;
}

__device__ __forceinline__ void cp_async16(uint32_t dst, const void* src, bool valid) {
    int sz = valid ? 16 : 0;
    asm volatile("cp.async.cg.shared.global [%0], [%1], 16, %2;"
                 :: "r"(dst), "l"(src), "r"(sz) : "memory");
}
#define CP_COMMIT()  asm volatile("cp.async.commit_group;" ::: "memory")
#define CP_WAIT_1()  asm volatile("cp.async.wait_group 1;" ::: "memory")
#define CP_WAIT_0()  asm volatile("cp.async.wait_group 0;" ::: "memory")

__device__ __forceinline__ void mma_tf32(float4& d, const uint32_t* a, const uint32_t* b) {
    asm volatile(
        "mma.sync.aligned.m16n8k8.row.col.f32.tf32.tf32.f32 "
        "{%0,%1,%2,%3}, {%4,%5,%6,%7}, {%8,%9}, {%0,%1,%2,%3};"
        : "+f"(d.x), "+f"(d.y), "+f"(d.z), "+f"(d.w)
        : "r"(a[0]), "r"(a[1]), "r"(a[2]), "r"(a[3]), "r"(b[0]), "r"(b[1]));
}

// smem layout: tile rows of 32 floats (128B), 16B groups XOR-swizzled by row.
// float index of logical (row, k):
__device__ __forceinline__ int sw(int row, int k) {
    return row * 32 + ((((k >> 2) ^ row) & 7) << 2) + (k & 3);
}

// ============================ GEMM kernel ===================================
// 128x128 CTA tile, BK=32, 8 warps (2M x 4N), warp tile 64x32, double buffer.

#define A_TILE_F 4096          // 128 * 32 floats
#define STAGE_F  8192          // A + B
#define SMEM_BYTES (2 * STAGE_F * 4)

template<bool BIAS, bool RELU, bool ROUND>
__global__ __launch_bounds__(256, 2)
void gemm_mma(const float* __restrict__ A, const float* __restrict__ B,
              const float* __restrict__ bias, float* __restrict__ C,
              int M, int N, int K, int lda, int ldb, int ldc)
{
    extern __shared__ float smf[];
    const uint32_t smem_base = smem_u32(smf);

    const int tid = threadIdx.x;
    const int wid = tid >> 5;
    const int lid = tid & 31;
    const int r   = lid >> 2;     // 0..7
    const int c   = lid & 3;      // 0..3
    const int bm  = blockIdx.y * 128;
    const int bn  = blockIdx.x * 128;
    const int m0  = (wid & 1) * 64;
    const int n0  = (wid >> 1) * 32;

    // loader assignments: 4 chunks of A + 4 of B per thread per stage
    int lrowA[4], lcgA[4];
#pragma unroll
    for (int i = 0; i < 4; i++) {
        int q = tid + i * 256;        // 0..1023
        lrowA[i] = q >> 3;
        lcgA[i]  = q & 7;
    }

    float4 acc[4][4];
#pragma unroll
    for (int i = 0; i < 4; i++)
#pragma unroll
        for (int j = 0; j < 4; j++) acc[i][j] = make_float4(0.f, 0.f, 0.f, 0.f);

    const int T = K >> 5;   // K / 32

    // ---- stage loader ----
    auto load_stage = [&](int t, int buf) {
        const int kblk = t * 32;
        uint32_t sA = smem_base + (buf * STAGE_F) * 4;
        uint32_t sB = sA + A_TILE_F * 4;
#pragma unroll
        for (int i = 0; i < 4; i++) {
            int row = lrowA[i], cg = lcgA[i];
            int gm = bm + row;
            bool v = gm < M;
            const float* src = A + (size_t)(v ? gm : 0) * lda + kblk + cg * 4;
            cp_async16(sA + (uint32_t)(sw(row, cg * 4)) * 4, src, v);
        }
#pragma unroll
        for (int i = 0; i < 4; i++) {
            int row = lrowA[i], cg = lcgA[i];
            int gn = bn + row;
            bool v = gn < N;
            const float* src = B + (size_t)(v ? gn : 0) * ldb + kblk + cg * 4;
            cp_async16(sB + (uint32_t)(sw(row, cg * 4)) * 4, src, v);
        }
        CP_COMMIT();
    };

    load_stage(0, 0);

    for (int t = 0; t < T; t++) {
        if (t + 1 < T) {
            load_stage(t + 1, (t + 1) & 1);
            CP_WAIT_1();
        } else {
            CP_WAIT_0();
        }
        __syncthreads();

        const float* As = smf + (t & 1) * STAGE_F;
        const float* Bs = As + A_TILE_F;
        const uint32_t* Asu = (const uint32_t*)As;
        const uint32_t* Bsu = (const uint32_t*)Bs;

#pragma unroll
        for (int kc = 0; kc < 4; kc++) {
            const int k0 = kc * 8;
            uint32_t af[4][4], bf[4][2];
#pragma unroll
            for (int i = 0; i < 4; i++) {
                int R = m0 + i * 16 + r;
                af[i][0] = Asu[sw(R,     k0 + c)];
                af[i][1] = Asu[sw(R + 8, k0 + c)];
                af[i][2] = Asu[sw(R,     k0 + c + 4)];
                af[i][3] = Asu[sw(R + 8, k0 + c + 4)];
            }
#pragma unroll
            for (int j = 0; j < 4; j++) {
                int Rb = n0 + j * 8 + r;
                bf[j][0] = Bsu[sw(Rb, k0 + c)];
                bf[j][1] = Bsu[sw(Rb, k0 + c + 4)];
            }
#pragma unroll
            for (int i = 0; i < 4; i++)
#pragma unroll
                for (int j = 0; j < 4; j++)
                    mma_tf32(acc[i][j], af[i], bf[j]);
        }
        __syncthreads();
    }

    // ---- epilogue: bias + relu + (tf32 round) + float2 stores --------------
#pragma unroll
    for (int i = 0; i < 4; i++) {
        int gm0 = bm + m0 + i * 16 + r;
#pragma unroll
        for (int j = 0; j < 4; j++) {
            int gn = bn + n0 + j * 8 + 2 * c;
            if (gn >= N) continue;
            float b0 = 0.f, b1 = 0.f;
            if (BIAS) { b0 = __ldg(&bias[gn]); b1 = __ldg(&bias[gn + 1]); }
            float4 v = acc[i][j];
            float x0 = v.x + b0, x1 = v.y + b1;
            float y0 = v.z + b0, y1 = v.w + b1;
            if (RELU) {
                x0 = fmaxf(x0, 0.f); x1 = fmaxf(x1, 0.f);
                y0 = fmaxf(y0, 0.f); y1 = fmaxf(y1, 0.f);
            }
            if (ROUND) {
                x0 = rna_tf32(x0); x1 = rna_tf32(x1);
                y0 = rna_tf32(y0); y1 = rna_tf32(y1);
            }
            if (gm0 < M)
                *(float2*)(&C[(size_t)gm0 * ldc + gn]) = make_float2(x0, x1);
            if (gm0 + 8 < M)
                *(float2*)(&C[(size_t)(gm0 + 8) * ldc + gn]) = make_float2(y0, y1);
        }
    }
}

// ============================ prep kernels ==================================

__global__ void round_pad_kernel(const float* __restrict__ src, float* __restrict__ dst,
                                 int rows, int cols, int dstride)
{
    int total = rows * dstride;
    for (int i = blockIdx.x * blockDim.x + threadIdx.x; i < total; i += gridDim.x * blockDim.x) {
        int rr = i / dstride, cc = i - rr * dstride;
        float v = 0.0f;
        if (cc < cols) v = rna_tf32(src[(size_t)rr * cols + cc]);
        dst[i] = v;
    }
}

__global__ void transpose_round_kernel(const float* __restrict__ src, float* __restrict__ dst)
{
    __shared__ float t[32][33];
    int nb = blockIdx.x * 32;
    int kb = blockIdx.y * 32;
    int x = threadIdx.x, y = threadIdx.y;   // 32 x 8
#pragma unroll
    for (int yy = y; yy < 32; yy += 8) {
        int k = kb + yy, n = nb + x;
        float v = 0.0f;
        if (k < SIZE_M && n < SIZE_N) v = rna_tf32(src[(size_t)k * SIZE_N + n]);
        t[yy][x] = v;
    }
    __syncthreads();
#pragma unroll
    for (int yy = y; yy < 32; yy += 8) {
        int n = nb + yy, k = kb + x;
        if (n < SIZE_N && k < K_PAD) dst[(size_t)n * K_PAD + k] = t[x][yy];
    }
}

// ============================ host side =====================================

static inline dim3 grid_for(int M, int N) {
    return dim3((N + 127) / 128, (M + 127) / 128);
}

extern "C" void kernel_launch(void* const* d_in, const int* in_sizes, int n_in,
                              void* d_out, int out_size)
{
    const float* x  = (const float*)d_in[0];   // [4096, 2048]
    const float* V1 = (const float*)d_in[1];   // [5794, 2897]
    const float* V2 = (const float*)d_in[2];   // [2897, 5794]
    float* out = (float*)d_out;                // [4096, 2048]

    float *V1r, *V2T, *xr, *Vf, *h1, *h2;
    cudaGetSymbolAddress((void**)&V1r, g_V1r);
    cudaGetSymbolAddress((void**)&V2T, g_V2T);
    cudaGetSymbolAddress((void**)&xr,  g_xr);
    cudaGetSymbolAddress((void**)&Vf,  g_Vf);
    cudaGetSymbolAddress((void**)&h1,  g_h1);
    cudaGetSymbolAddress((void**)&h2,  g_h2);

    // prep: unbiased tf32 rounding (+pad / +transpose)
    round_pad_kernel<<<2048, 256>>>(V1, V1r, SIZE_N, SIZE_M, K_PAD);
    round_pad_kernel<<<2048, 256>>>(x, xr, BATCH, D_IN, D_IN);
    transpose_round_kernel<<<dim3((SIZE_N + 31) / 32, (K_PAD + 31) / 32), dim3(32, 8)>>>(V2, V2T);

    cudaFuncSetAttribute(gemm_mma<false, false, true>,
                         cudaFuncAttributeMaxDynamicSharedMemorySize, SMEM_BYTES);
    cudaFuncSetAttribute(gemm_mma<true, true, true>,
                         cudaFuncAttributeMaxDynamicSharedMemorySize, SMEM_BYTES);
    cudaFuncSetAttribute(gemm_mma<true, false, false>,
                         cudaFuncAttributeMaxDynamicSharedMemorySize, SMEM_BYTES);

    // 1) Vf = V1r @ V2T^T   M=N=5794, K=2912 (padded), round stores to tf32
    gemm_mma<false, false, true><<<grid_for(SIZE_N, SIZE_N), 256, SMEM_BYTES>>>(
        V1r, V2T, nullptr, Vf, SIZE_N, SIZE_N, K_PAD, K_PAD, K_PAD, SIZE_N);

    // 2) h1 = relu(xr @ W1^T + b1), rounded
    gemm_mma<true, true, true><<<grid_for(BATCH, D_H), 256, SMEM_BYTES>>>(
        xr, Vf + OFF_W1, Vf + OFF_B1, h1, BATCH, D_H, D_IN, D_IN, D_IN, D_H);

    // 3) h2 = relu(h1 @ W2^T + b2), rounded
    gemm_mma<true, true, true><<<grid_for(BATCH, D_H), 256, SMEM_BYTES>>>(
        h1, Vf + OFF_W2, Vf + OFF_B2, h2, BATCH, D_H, D_H, D_H, D_H, D_H);

    // 4) out = h2 @ W3^T + b3 (fp32 out)
    gemm_mma<true, false, false><<<grid_for(BATCH, D_OUT), 256, SMEM_BYTES>>>(
        h2, Vf + OFF_W3, Vf + OFF_B3, out, BATCH, D_OUT, D_H, D_H, D_H, D_OUT);
}